// round 14
// baseline (speedup 1.0000x reference)
#include <cuda_runtime.h>
#include <cuda_fp16.h>
#include <cstdint>

// out = x + exp(-max(||qi||^2 - 2<qi,kj> + ||kj||^2, 0)*sigma) @ x
// B=32, T=2048, C=64 fp32.
// Pure fp16 mma.sync, M_warp=32 (TQ=256): halves ldmatrix traffic per MMA.
// Norms pre-scaled by -sigma*log2(e); w = ex2(min(nq+nk+p2*s,0)).
// Double-buffered K tiles, chunked register prefetch, hoisted Q fragments,
// 1 sync/tile, 2 CTAs/SM.

#define BATCH   32
#define TDIM    2048
#define CDIM    64
#define TQ      256
#define TK      128
#define NTILES  (TDIM / TK)
#define THREADS 256

#define RSTRB       144               // 72 fp16 row stride
#define OFF_Q       0                 // Q tile: 256*144 = 36864 B
#define OFF_K       36864             // K buffers: + buf*18432
#define KBUF_STRIDE 18432
#define OFF_SQK     73728             // 2 x 128 floats (double-buffered, pre-scaled)
#define OFF_SQQ     74752             // 256 floats (pre-scaled)
#define SMEM_DYN    75776

__device__ __forceinline__ uint32_t smem_u32(const void* p) {
    uint32_t a;
    asm("{ .reg .u64 t; cvta.to.shared.u64 t, %1; cvt.u32.u64 %0, t; }" : "=r"(a) : "l"(p));
    return a;
}

__device__ __forceinline__ float ex2(float x) {
    float r;
    asm("ex2.approx.ftz.f32 %0, %1;" : "=f"(r) : "f"(x));
    return r;
}

#define LDSM_X4(r, addr) \
    asm volatile("ldmatrix.sync.aligned.m8n8.x4.shared.b16 {%0,%1,%2,%3}, [%4];" \
        : "=r"((r)[0]), "=r"((r)[1]), "=r"((r)[2]), "=r"((r)[3]) : "r"(addr))

#define LDSM_X4_T(r, addr) \
    asm volatile("ldmatrix.sync.aligned.m8n8.x4.trans.shared.b16 {%0,%1,%2,%3}, [%4];" \
        : "=r"((r)[0]), "=r"((r)[1]), "=r"((r)[2]), "=r"((r)[3]) : "r"(addr))

#define MMA(dv, a, b0, b1) \
    asm volatile("mma.sync.aligned.m16n8k16.row.col.f32.f16.f16.f32 " \
        "{%0,%1,%2,%3}, {%4,%5,%6,%7}, {%8,%9}, {%0,%1,%2,%3};" \
        : "+f"((dv)[0]), "+f"((dv)[1]), "+f"((dv)[2]), "+f"((dv)[3]) \
        : "r"((a)[0]), "r"((a)[1]), "r"((a)[2]), "r"((a)[3]), "r"(b0), "r"(b1))

__device__ __forceinline__ uint32_t pack_hi(float a, float b) {
    __half2 h2 = __floats2half2_rn(a, b);
    return *reinterpret_cast<uint32_t*>(&h2);
}

__global__ __launch_bounds__(THREADS, 2)
void k_attention_mma7(const float* __restrict__ x,
                      const float* __restrict__ r_sigma,
                      float* __restrict__ out) {
    extern __shared__ char sm[];
    const uint32_t sb = smem_u32(sm);
    float* sqqArr = reinterpret_cast<float*>(sm + OFF_SQQ);

    const int tid   = threadIdx.x;
    const int lane  = tid & 31;
    const int wid   = tid >> 5;
    const int wbase = wid * 32;        // 32 query rows per warp
    const int g     = lane >> 2;
    const int t2    = (lane & 3) * 2;
    const int gr16  = tid >> 4;
    const int c4    = tid & 15;

    const int b     = blockIdx.y;
    const int qbase = blockIdx.x * TQ;
    const float* xb = x + (size_t)b * TDIM * CDIM;
    float* ob       = out + (size_t)b * TDIM * CDIM;
    const float negs2 = -r_sigma[0] * 1.4426950408889634f;   // -sigma*log2(e)
    const float p2    = -2.f * negs2;

    const uint32_t kAddrH = sb + OFF_K + (uint32_t)((lane & 7) + ((lane >> 4) << 3)) * RSTRB
                            + ((lane >> 3) & 1) * 16;
    const uint32_t xAddrH = sb + OFF_K + (uint32_t)(lane & 15) * RSTRB + (lane >> 4) * 16;

    // ---- prologue: Q tile (256 rows, fp16) ----
    #pragma unroll
    for (int i = 0; i < 16; ++i) {
        int idx = tid + i * THREADS;
        int r = idx >> 4, cc = idx & 15;
        float4 v = *reinterpret_cast<const float4*>(&xb[(qbase + r) * CDIM + cc * 4]);
        uint32_t off = (uint32_t)r * RSTRB + (uint32_t)cc * 8;
        *reinterpret_cast<uint2*>(sm + OFF_Q + off) =
            make_uint2(pack_hi(v.x, v.y), pack_hi(v.z, v.w));
    }
    // ---- prologue: K tile 0 into buf0 + pre-scaled key norms ----
    {
        float p[8];
        #pragma unroll
        for (int i = 0; i < 8; ++i) {
            int r = gr16 + 16 * i;
            float4 v = *reinterpret_cast<const float4*>(&xb[r * CDIM + c4 * 4]);
            uint32_t off = (uint32_t)r * RSTRB + (uint32_t)c4 * 8;
            *reinterpret_cast<uint2*>(sm + OFF_K + off) =
                make_uint2(pack_hi(v.x, v.y), pack_hi(v.z, v.w));
            p[i] = fmaf(v.x, v.x, fmaf(v.y, v.y, fmaf(v.z, v.z, v.w * v.w)));
        }
        #pragma unroll
        for (int i = 0; i < 8; ++i) {
            #pragma unroll
            for (int m = 1; m < 16; m <<= 1)
                p[i] += __shfl_xor_sync(0xFFFFFFFFu, p[i], m);
        }
        if (c4 == 0) {
            float* sk0 = reinterpret_cast<float*>(sm + OFF_SQK);
            #pragma unroll
            for (int i = 0; i < 8; ++i) sk0[gr16 + 16 * i] = negs2 * p[i];
        }
    }
    // ---- prologue: pre-scaled query norms (256 rows) ----
    {
        const float4* qr = reinterpret_cast<const float4*>(&xb[(qbase + tid) * CDIM]);
        float s = 0.f;
        #pragma unroll
        for (int i = 0; i < 16; ++i) {
            float4 v = qr[i];
            s = fmaf(v.x, v.x, fmaf(v.y, v.y, fmaf(v.z, v.z, fmaf(v.w, v.w, s))));
        }
        sqqArr[tid] = negs2 * s;
    }
    __syncthreads();

    // pre-scaled query norms for this warp's 4 row-groups
    const float nq[4] = { sqqArr[wbase + g],      sqqArr[wbase + g + 8],
                          sqqArr[wbase + 16 + g], sqqArr[wbase + 24 + g] };

    // ---- Q fragments (2 msubs x 4 kc), loaded once ----
    uint32_t aH[2][4][4];
    #pragma unroll
    for (int m = 0; m < 2; ++m) {
        uint32_t qa = sb + OFF_Q + (uint32_t)(wbase + m * 16 + (lane & 15)) * RSTRB
                      + (lane >> 4) * 16;
        #pragma unroll
        for (int kc = 0; kc < 4; ++kc) LDSM_X4(aH[m][kc], qa + kc * 32);
    }

    float oacc[2][8][4];
    #pragma unroll
    for (int m = 0; m < 2; ++m)
        #pragma unroll
        for (int i = 0; i < 8; ++i)
            #pragma unroll
            for (int j = 0; j < 4; ++j) oacc[m][i][j] = 0.f;

    for (int kt = 0; kt < NTILES; ++kt) {
        const uint32_t bufOff  = (uint32_t)(kt & 1) * KBUF_STRIDE;
        const uint32_t nbufOff = bufOff ^ KBUF_STRIDE;
        const float* skb = reinterpret_cast<const float*>(sm + OFF_SQK + (kt & 1) * 512);
        float* skn       = reinterpret_cast<float*>(sm + OFF_SQK + ((kt & 1) ^ 1) * 512);
        const bool haveNext = (kt + 1) < NTILES;
        const int nkbase = (kt + 1) * TK;

        float p[8];

        auto process_np = [&](int np) {
            float s[4][4];   // [msub*2 + nhalf][4]
            #pragma unroll
            for (int i = 0; i < 4; ++i)
                #pragma unroll
                for (int j = 0; j < 4; ++j) s[i][j] = 0.f;
            #pragma unroll
            for (int kc = 0; kc < 4; ++kc) {
                uint32_t bH[4];
                LDSM_X4(bH, kAddrH + bufOff + (uint32_t)np * 2304 + kc * 32);
                MMA(s[0], aH[0][kc], bH[0], bH[1]);
                MMA(s[1], aH[0][kc], bH[2], bH[3]);
                MMA(s[2], aH[1][kc], bH[0], bH[1]);
                MMA(s[3], aH[1][kc], bH[2], bH[3]);
            }
            float nk0 = skb[np * 16 + t2];
            float nk1 = skb[np * 16 + t2 + 1];
            float nk2 = skb[np * 16 + 8 + t2];
            float nk3 = skb[np * 16 + 8 + t2 + 1];

            uint32_t wh[2][4];
            #pragma unroll
            for (int m = 0; m < 2; ++m) {
                float a0 = nq[2 * m], a1 = nq[2 * m + 1];
                float w00 = ex2(fminf(fmaf(p2, s[2 * m][0], a0 + nk0), 0.f));
                float w01 = ex2(fminf(fmaf(p2, s[2 * m][1], a0 + nk1), 0.f));
                float w02 = ex2(fminf(fmaf(p2, s[2 * m][2], a1 + nk0), 0.f));
                float w03 = ex2(fminf(fmaf(p2, s[2 * m][3], a1 + nk1), 0.f));
                float w10 = ex2(fminf(fmaf(p2, s[2 * m + 1][0], a0 + nk2), 0.f));
                float w11 = ex2(fminf(fmaf(p2, s[2 * m + 1][1], a0 + nk3), 0.f));
                float w12 = ex2(fminf(fmaf(p2, s[2 * m + 1][2], a1 + nk2), 0.f));
                float w13 = ex2(fminf(fmaf(p2, s[2 * m + 1][3], a1 + nk3), 0.f));
                wh[m][0] = pack_hi(w00, w01);
                wh[m][1] = pack_hi(w02, w03);
                wh[m][2] = pack_hi(w10, w11);
                wh[m][3] = pack_hi(w12, w13);
            }

            #pragma unroll
            for (int cp = 0; cp < 4; ++cp) {
                uint32_t bX[4];
                LDSM_X4_T(bX, xAddrH + bufOff + (uint32_t)np * 2304 + cp * 32);
                MMA(oacc[0][2 * cp],     wh[0], bX[0], bX[1]);
                MMA(oacc[0][2 * cp + 1], wh[0], bX[2], bX[3]);
                MMA(oacc[1][2 * cp],     wh[1], bX[0], bX[1]);
                MMA(oacc[1][2 * cp + 1], wh[1], bX[2], bX[3]);
            }
        };

        // 4 chunks: prefetch 2 row-groups, run 2 np's, convert+store them
        #pragma unroll
        for (int h = 0; h < 4; ++h) {
            float4 pf0, pf1;
            if (haveNext) {
                int r0 = gr16 + 16 * (2 * h);
                int r1 = gr16 + 16 * (2 * h + 1);
                pf0 = *reinterpret_cast<const float4*>(&xb[(nkbase + r0) * CDIM + c4 * 4]);
                pf1 = *reinterpret_cast<const float4*>(&xb[(nkbase + r1) * CDIM + c4 * 4]);
            }
            process_np(2 * h);
            process_np(2 * h + 1);
            if (haveNext) {
                int r0 = gr16 + 16 * (2 * h);
                int r1 = gr16 + 16 * (2 * h + 1);
                uint32_t o0 = (uint32_t)r0 * RSTRB + (uint32_t)c4 * 8;
                uint32_t o1 = (uint32_t)r1 * RSTRB + (uint32_t)c4 * 8;
                *reinterpret_cast<uint2*>(sm + OFF_K + nbufOff + o0) =
                    make_uint2(pack_hi(pf0.x, pf0.y), pack_hi(pf0.z, pf0.w));
                *reinterpret_cast<uint2*>(sm + OFF_K + nbufOff + o1) =
                    make_uint2(pack_hi(pf1.x, pf1.y), pack_hi(pf1.z, pf1.w));
                p[2 * h]     = fmaf(pf0.x, pf0.x, fmaf(pf0.y, pf0.y, fmaf(pf0.z, pf0.z, pf0.w * pf0.w)));
                p[2 * h + 1] = fmaf(pf1.x, pf1.x, fmaf(pf1.y, pf1.y, fmaf(pf1.z, pf1.z, pf1.w * pf1.w)));
            }
        }

        if (haveNext) {
            #pragma unroll
            for (int i = 0; i < 8; ++i) {
                #pragma unroll
                for (int m = 1; m < 16; m <<= 1)
                    p[i] += __shfl_xor_sync(0xFFFFFFFFu, p[i], m);
            }
            if (c4 == 0) {
                #pragma unroll
                for (int i = 0; i < 8; ++i) skn[gr16 + 16 * i] = negs2 * p[i];
            }
        }
        __syncthreads();
    }

    // ---- final: out = x + O ----
    #pragma unroll
    for (int m = 0; m < 2; ++m) {
        const int r0 = qbase + wbase + m * 16 + g;
        const int r1 = r0 + 8;
        #pragma unroll
        for (int nt = 0; nt < 8; ++nt) {
            int c = nt * 8 + t2;
            float2 x0 = *reinterpret_cast<const float2*>(&xb[r0 * CDIM + c]);
            float2 x1 = *reinterpret_cast<const float2*>(&xb[r1 * CDIM + c]);
            float2 o0 = make_float2(x0.x + oacc[m][nt][0], x0.y + oacc[m][nt][1]);
            float2 o1 = make_float2(x1.x + oacc[m][nt][2], x1.y + oacc[m][nt][3]);
            *reinterpret_cast<float2*>(&ob[r0 * CDIM + c]) = o0;
            *reinterpret_cast<float2*>(&ob[r1 * CDIM + c]) = o1;
        }
    }
}

extern "C" void kernel_launch(void* const* d_in, const int* in_sizes, int n_in,
                              void* d_out, int out_size) {
    const float* x       = (const float*)d_in[0];
    const float* r_sigma = (const float*)d_in[1];
    float* out           = (float*)d_out;

    cudaFuncSetAttribute(k_attention_mma7,
                         cudaFuncAttributeMaxDynamicSharedMemorySize, SMEM_DYN);

    dim3 grid(TDIM / TQ, BATCH);
    k_attention_mma7<<<grid, THREADS, SMEM_DYN>>>(x, r_sigma, out);
}

// round 15
// speedup vs baseline: 1.0953x; 1.0953x over previous
#include <cuda_runtime.h>
#include <cuda_fp16.h>
#include <cstdint>

// out = x + exp(-max(||qi||^2 - 2<qi,kj> + ||kj||^2, 0)*sigma) @ x
// B=32, T=2048, C=64 fp32.
// Pure fp16 mma.sync, TQ=128.  GEMM2 B-fragments derived from GEMM1's K
// fragments via movmatrix (in-register 8x8 transpose) -> X-side ldmatrix
// traffic eliminated.  Norms pre-scaled by -sigma*log2(e);
// w = ex2(min(nq+nk+p2*s,0)).  Double-buffered K tiles, streamed tail
// conversion, hoisted Q fragments, 1 sync/tile, 3 CTAs/SM.

#define BATCH   32
#define TDIM    2048
#define CDIM    64
#define TQ      128
#define TK      128
#define NTILES  (TDIM / TK)
#define THREADS 256

#define RSTRB       144               // 72 fp16 row stride
#define OFF_Q       0                 // Q tile (18432 B)
#define OFF_K       18432             // K buffers: + buf*18432
#define KBUF_STRIDE 18432
#define OFF_SQK     55296             // 2 x 128 floats (double-buffered, pre-scaled)
#define OFF_SQQ     56320             // 128 floats (pre-scaled)
#define SMEM_DYN    56832

__device__ __forceinline__ uint32_t smem_u32(const void* p) {
    uint32_t a;
    asm("{ .reg .u64 t; cvta.to.shared.u64 t, %1; cvt.u32.u64 %0, t; }" : "=r"(a) : "l"(p));
    return a;
}

__device__ __forceinline__ float ex2(float x) {
    float r;
    asm("ex2.approx.ftz.f32 %0, %1;" : "=f"(r) : "f"(x));
    return r;
}

#define LDSM_X4(r, addr) \
    asm volatile("ldmatrix.sync.aligned.m8n8.x4.shared.b16 {%0,%1,%2,%3}, [%4];" \
        : "=r"((r)[0]), "=r"((r)[1]), "=r"((r)[2]), "=r"((r)[3]) : "r"(addr))

#define MOVM_T(d, a) \
    asm volatile("movmatrix.sync.aligned.m8n8.trans.b16 %0, %1;" : "=r"(d) : "r"(a))

#define MMA(dv, a, b0, b1) \
    asm volatile("mma.sync.aligned.m16n8k16.row.col.f32.f16.f16.f32 " \
        "{%0,%1,%2,%3}, {%4,%5,%6,%7}, {%8,%9}, {%0,%1,%2,%3};" \
        : "+f"((dv)[0]), "+f"((dv)[1]), "+f"((dv)[2]), "+f"((dv)[3]) \
        : "r"((a)[0]), "r"((a)[1]), "r"((a)[2]), "r"((a)[3]), "r"(b0), "r"(b1))

__device__ __forceinline__ uint32_t pack_hi(float a, float b) {
    __half2 h2 = __floats2half2_rn(a, b);
    return *reinterpret_cast<uint32_t*>(&h2);
}

__global__ __launch_bounds__(THREADS, 3)
void k_attention_mma8(const float* __restrict__ x,
                      const float* __restrict__ r_sigma,
                      float* __restrict__ out) {
    extern __shared__ char sm[];
    const uint32_t sb = smem_u32(sm);
    float* sqqArr = reinterpret_cast<float*>(sm + OFF_SQQ);

    const int tid   = threadIdx.x;
    const int lane  = tid & 31;
    const int wid   = tid >> 5;
    const int wbase = wid * 16;
    const int g     = lane >> 2;
    const int t2    = (lane & 3) * 2;
    const int gr16  = tid >> 4;
    const int c4    = tid & 15;

    const int b     = blockIdx.y;
    const int qbase = blockIdx.x * TQ;
    const float* xb = x + (size_t)b * TDIM * CDIM;
    float* ob       = out + (size_t)b * TDIM * CDIM;
    const float negs2 = -r_sigma[0] * 1.4426950408889634f;   // -sigma*log2(e)
    const float p2    = -2.f * negs2;

    const uint32_t qAddr  = sb + OFF_Q + (uint32_t)(wbase + (lane & 15)) * RSTRB + (lane >> 4) * 16;
    const uint32_t kAddrH = sb + OFF_K + (uint32_t)((lane & 7) + ((lane >> 4) << 3)) * RSTRB
                            + ((lane >> 3) & 1) * 16;

    // ---- prologue: Q tile (fp16) ----
    #pragma unroll
    for (int i = 0; i < 8; ++i) {
        int r = gr16 + 16 * i;
        float4 v = *reinterpret_cast<const float4*>(&xb[(qbase + r) * CDIM + c4 * 4]);
        uint32_t off = (uint32_t)r * RSTRB + (uint32_t)c4 * 8;
        *reinterpret_cast<uint2*>(sm + OFF_Q + off) =
            make_uint2(pack_hi(v.x, v.y), pack_hi(v.z, v.w));
    }
    // ---- prologue: K tile 0 into buf0 + pre-scaled key norms ----
    #pragma unroll
    for (int i = 0; i < 8; ++i) {
        int r = gr16 + 16 * i;
        float4 v = *reinterpret_cast<const float4*>(&xb[r * CDIM + c4 * 4]);
        uint32_t off = (uint32_t)r * RSTRB + (uint32_t)c4 * 8;
        *reinterpret_cast<uint2*>(sm + OFF_K + off) =
            make_uint2(pack_hi(v.x, v.y), pack_hi(v.z, v.w));
        float pi = fmaf(v.x, v.x, fmaf(v.y, v.y, fmaf(v.z, v.z, v.w * v.w)));
        #pragma unroll
        for (int m = 1; m < 16; m <<= 1)
            pi += __shfl_xor_sync(0xFFFFFFFFu, pi, m);
        if (c4 == 0)
            reinterpret_cast<float*>(sm + OFF_SQK)[r] = negs2 * pi;
    }
    // ---- prologue: pre-scaled query norms ----
    if (tid < 128) {
        const float4* qr = reinterpret_cast<const float4*>(&xb[(qbase + tid) * CDIM]);
        float s = 0.f;
        #pragma unroll
        for (int i = 0; i < 16; ++i) {
            float4 v = qr[i];
            s = fmaf(v.x, v.x, fmaf(v.y, v.y, fmaf(v.z, v.z, fmaf(v.w, v.w, s))));
        }
        sqqArr[tid] = negs2 * s;
    }
    __syncthreads();

    const float nq0 = sqqArr[wbase + g];        // pre-scaled
    const float nq1 = sqqArr[wbase + g + 8];

    // ---- Q fragments, loaded once ----
    uint32_t aH[4][4];
    #pragma unroll
    for (int kc = 0; kc < 4; ++kc) LDSM_X4(aH[kc], qAddr + kc * 32);

    float oacc[8][4];
    #pragma unroll
    for (int i = 0; i < 8; ++i)
        #pragma unroll
        for (int j = 0; j < 4; ++j) oacc[i][j] = 0.f;

    for (int kt = 0; kt < NTILES; ++kt) {
        const uint32_t bufOff  = (uint32_t)(kt & 1) * KBUF_STRIDE;
        const uint32_t nbufOff = bufOff ^ KBUF_STRIDE;
        const float* skb = reinterpret_cast<const float*>(sm + OFF_SQK + (kt & 1) * 512);
        float* skn       = reinterpret_cast<float*>(sm + OFF_SQK + ((kt & 1) ^ 1) * 512);
        const bool haveNext = (kt + 1) < NTILES;
        const int nkbase = (kt + 1) * TK;

        #pragma unroll
        for (int np = 0; np < 8; ++np) {
            float s0[4] = {0.f, 0.f, 0.f, 0.f};
            float s1[4] = {0.f, 0.f, 0.f, 0.f};
            uint32_t bT[4][4];                   // transposed K = X^T fragments
            #pragma unroll
            for (int kc = 0; kc < 4; ++kc) {
                uint32_t bH[4];
                LDSM_X4(bH, kAddrH + bufOff + (uint32_t)np * 2304 + kc * 32);
                MMA(s0, aH[kc], bH[0], bH[1]);
                MMA(s1, aH[kc], bH[2], bH[3]);
                // T(keys x cols) -> (cols x keys): GEMM2 B-pairs
                MOVM_T(bT[kc][0], bH[0]);   // cols 0:8  x keys 0:8
                MOVM_T(bT[kc][1], bH[2]);   // cols 0:8  x keys 8:16
                MOVM_T(bT[kc][2], bH[1]);   // cols 8:16 x keys 0:8
                MOVM_T(bT[kc][3], bH[3]);   // cols 8:16 x keys 8:16
            }
            float nk0 = skb[np * 16 + t2];
            float nk1 = skb[np * 16 + t2 + 1];
            float nk2 = skb[np * 16 + 8 + t2];
            float nk3 = skb[np * 16 + 8 + t2 + 1];
            float w00 = ex2(fminf(fmaf(p2, s0[0], nq0 + nk0), 0.f));
            float w01 = ex2(fminf(fmaf(p2, s0[1], nq0 + nk1), 0.f));
            float w02 = ex2(fminf(fmaf(p2, s0[2], nq1 + nk0), 0.f));
            float w03 = ex2(fminf(fmaf(p2, s0[3], nq1 + nk1), 0.f));
            float w10 = ex2(fminf(fmaf(p2, s1[0], nq0 + nk2), 0.f));
            float w11 = ex2(fminf(fmaf(p2, s1[1], nq0 + nk3), 0.f));
            float w12 = ex2(fminf(fmaf(p2, s1[2], nq1 + nk2), 0.f));
            float w13 = ex2(fminf(fmaf(p2, s1[3], nq1 + nk3), 0.f));

            uint32_t wh[4];
            wh[0] = pack_hi(w00, w01);
            wh[1] = pack_hi(w02, w03);
            wh[2] = pack_hi(w10, w11);
            wh[3] = pack_hi(w12, w13);

            #pragma unroll
            for (int cp = 0; cp < 4; ++cp) {
                MMA(oacc[2 * cp],     wh, bT[cp][0], bT[cp][1]);
                MMA(oacc[2 * cp + 1], wh, bT[cp][2], bT[cp][3]);
            }
        }

        // ---- tail: stream-convert next K tile + pre-scaled norms ----
        if (haveNext) {
            #pragma unroll
            for (int i = 0; i < 8; ++i) {
                int r = gr16 + 16 * i;
                float4 v = *reinterpret_cast<const float4*>(&xb[(nkbase + r) * CDIM + c4 * 4]);
                uint32_t off = (uint32_t)r * RSTRB + (uint32_t)c4 * 8;
                *reinterpret_cast<uint2*>(sm + OFF_K + nbufOff + off) =
                    make_uint2(pack_hi(v.x, v.y), pack_hi(v.z, v.w));
                float pi = fmaf(v.x, v.x, fmaf(v.y, v.y, fmaf(v.z, v.z, v.w * v.w)));
                #pragma unroll
                for (int m = 1; m < 16; m <<= 1)
                    pi += __shfl_xor_sync(0xFFFFFFFFu, pi, m);
                if (c4 == 0) skn[r] = negs2 * pi;
            }
        }
        __syncthreads();
    }

    // ---- final: out = x + O ----
    const int r0 = qbase + wbase + g;
    const int r1 = r0 + 8;
    #pragma unroll
    for (int nt = 0; nt < 8; ++nt) {
        int c = nt * 8 + t2;
        float2 x0 = *reinterpret_cast<const float2*>(&xb[r0 * CDIM + c]);
        float2 x1 = *reinterpret_cast<const float2*>(&xb[r1 * CDIM + c]);
        float2 o0 = make_float2(x0.x + oacc[nt][0], x0.y + oacc[nt][1]);
        float2 o1 = make_float2(x1.x + oacc[nt][2], x1.y + oacc[nt][3]);
        *reinterpret_cast<float2*>(&ob[r0 * CDIM + c]) = o0;
        *reinterpret_cast<float2*>(&ob[r1 * CDIM + c]) = o1;
    }
}

extern "C" void kernel_launch(void* const* d_in, const int* in_sizes, int n_in,
                              void* d_out, int out_size) {
    const float* x       = (const float*)d_in[0];
    const float* r_sigma = (const float*)d_in[1];
    float* out           = (float*)d_out;

    cudaFuncSetAttribute(k_attention_mma8,
                         cudaFuncAttributeMaxDynamicSharedMemorySize, SMEM_DYN);

    dim3 grid(TDIM / TQ, BATCH);
    k_attention_mma8<<<grid, THREADS, SMEM_DYN>>>(x, r_sigma, out);
}

// round 17
// speedup vs baseline: 1.1094x; 1.0129x over previous
#include <cuda_runtime.h>
#include <cuda_fp16.h>
#include <cstdint>

// out = x + exp(-max(||qi||^2 - 2<qi,kj> + ||kj||^2, 0)*sigma) @ x
// B=32, T=2048, C=64 fp32.
// Pure fp16 mma.sync, TQ=128.  GEMM2 B-fragments via movmatrix.
// Epilogue: args in fp32, packed to half2, clamped with hmin2, then
// ex2.approx.f16x2 (dual-half MUFU) -> wh directly.
// Double-buffered K tiles, streamed tail conversion, hoisted Q fragments,
// 1 sync/tile, 3 CTAs/SM.

#define BATCH   32
#define TDIM    2048
#define CDIM    64
#define TQ      128
#define TK      128
#define NTILES  (TDIM / TK)
#define THREADS 256

#define RSTRB       144               // 72 fp16 row stride
#define OFF_Q       0                 // Q tile (18432 B)
#define OFF_K       18432             // K buffers: + buf*18432
#define KBUF_STRIDE 18432
#define OFF_SQK     55296             // 2 x 128 floats (double-buffered, pre-scaled)
#define OFF_SQQ     56320             // 128 floats (pre-scaled)
#define SMEM_DYN    56832

__device__ __forceinline__ uint32_t smem_u32(const void* p) {
    uint32_t a;
    asm("{ .reg .u64 t; cvta.to.shared.u64 t, %1; cvt.u32.u64 %0, t; }" : "=r"(a) : "l"(p));
    return a;
}

#define LDSM_X4(r, addr) \
    asm volatile("ldmatrix.sync.aligned.m8n8.x4.shared.b16 {%0,%1,%2,%3}, [%4];" \
        : "=r"((r)[0]), "=r"((r)[1]), "=r"((r)[2]), "=r"((r)[3]) : "r"(addr))

#define MOVM_T(d, a) \
    asm volatile("movmatrix.sync.aligned.m8n8.trans.b16 %0, %1;" : "=r"(d) : "r"(a))

#define MMA(dv, a, b0, b1) \
    asm volatile("mma.sync.aligned.m16n8k16.row.col.f32.f16.f16.f32 " \
        "{%0,%1,%2,%3}, {%4,%5,%6,%7}, {%8,%9}, {%0,%1,%2,%3};" \
        : "+f"((dv)[0]), "+f"((dv)[1]), "+f"((dv)[2]), "+f"((dv)[3]) \
        : "r"((a)[0]), "r"((a)[1]), "r"((a)[2]), "r"((a)[3]), "r"(b0), "r"(b1))

__device__ __forceinline__ uint32_t pack_hi(float a, float b) {
    __half2 h2 = __floats2half2_rn(a, b);
    return *reinterpret_cast<uint32_t*>(&h2);
}

// w(half2) = ex2(min(pack(a,b), 0)) computed entirely on the f16x2 path
__device__ __forceinline__ uint32_t w_f16x2(float a, float b) {
    __half2 h = __floats2half2_rn(a, b);                 // cvt.rn.f16x2.f32
    h = __hmin2(h, __half2half2(__ushort_as_half(0)));   // clamp exponent arg <= 0
    uint32_t hu = *reinterpret_cast<uint32_t*>(&h);
    uint32_t r;
    asm("ex2.approx.f16x2 %0, %1;" : "=r"(r) : "r"(hu));
    return r;
}

__global__ __launch_bounds__(THREADS, 3)
void k_attention_mma9(const float* __restrict__ x,
                      const float* __restrict__ r_sigma,
                      float* __restrict__ out) {
    extern __shared__ char sm[];
    const uint32_t sb = smem_u32(sm);
    float* sqqArr = reinterpret_cast<float*>(sm + OFF_SQQ);

    const int tid   = threadIdx.x;
    const int lane  = tid & 31;
    const int wid   = tid >> 5;
    const int wbase = wid * 16;
    const int g     = lane >> 2;
    const int t2    = (lane & 3) * 2;
    const int gr16  = tid >> 4;
    const int c4    = tid & 15;

    const int b     = blockIdx.y;
    const int qbase = blockIdx.x * TQ;
    const float* xb = x + (size_t)b * TDIM * CDIM;
    float* ob       = out + (size_t)b * TDIM * CDIM;
    const float negs2 = -r_sigma[0] * 1.4426950408889634f;   // -sigma*log2(e)
    const float p2    = -2.f * negs2;

    const uint32_t qAddr  = sb + OFF_Q + (uint32_t)(wbase + (lane & 15)) * RSTRB + (lane >> 4) * 16;
    const uint32_t kAddrH = sb + OFF_K + (uint32_t)((lane & 7) + ((lane >> 4) << 3)) * RSTRB
                            + ((lane >> 3) & 1) * 16;

    // ---- prologue: Q tile (fp16) ----
    #pragma unroll
    for (int i = 0; i < 8; ++i) {
        int r = gr16 + 16 * i;
        float4 v = *reinterpret_cast<const float4*>(&xb[(qbase + r) * CDIM + c4 * 4]);
        uint32_t off = (uint32_t)r * RSTRB + (uint32_t)c4 * 8;
        *reinterpret_cast<uint2*>(sm + OFF_Q + off) =
            make_uint2(pack_hi(v.x, v.y), pack_hi(v.z, v.w));
    }
    // ---- prologue: K tile 0 into buf0 + pre-scaled key norms ----
    #pragma unroll
    for (int i = 0; i < 8; ++i) {
        int r = gr16 + 16 * i;
        float4 v = *reinterpret_cast<const float4*>(&xb[r * CDIM + c4 * 4]);
        uint32_t off = (uint32_t)r * RSTRB + (uint32_t)c4 * 8;
        *reinterpret_cast<uint2*>(sm + OFF_K + off) =
            make_uint2(pack_hi(v.x, v.y), pack_hi(v.z, v.w));
        float pi = fmaf(v.x, v.x, fmaf(v.y, v.y, fmaf(v.z, v.z, v.w * v.w)));
        #pragma unroll
        for (int m = 1; m < 16; m <<= 1)
            pi += __shfl_xor_sync(0xFFFFFFFFu, pi, m);
        if (c4 == 0)
            reinterpret_cast<float*>(sm + OFF_SQK)[r] = negs2 * pi;
    }
    // ---- prologue: pre-scaled query norms ----
    if (tid < 128) {
        const float4* qr = reinterpret_cast<const float4*>(&xb[(qbase + tid) * CDIM]);
        float s = 0.f;
        #pragma unroll
        for (int i = 0; i < 16; ++i) {
            float4 v = qr[i];
            s = fmaf(v.x, v.x, fmaf(v.y, v.y, fmaf(v.z, v.z, fmaf(v.w, v.w, s))));
        }
        sqqArr[tid] = negs2 * s;
    }
    __syncthreads();

    const float nq0 = sqqArr[wbase + g];        // pre-scaled
    const float nq1 = sqqArr[wbase + g + 8];

    // ---- Q fragments, loaded once ----
    uint32_t aH[4][4];
    #pragma unroll
    for (int kc = 0; kc < 4; ++kc) LDSM_X4(aH[kc], qAddr + kc * 32);

    float oacc[8][4];
    #pragma unroll
    for (int i = 0; i < 8; ++i)
        #pragma unroll
        for (int j = 0; j < 4; ++j) oacc[i][j] = 0.f;

    for (int kt = 0; kt < NTILES; ++kt) {
        const uint32_t bufOff  = (uint32_t)(kt & 1) * KBUF_STRIDE;
        const uint32_t nbufOff = bufOff ^ KBUF_STRIDE;
        const float* skb = reinterpret_cast<const float*>(sm + OFF_SQK + (kt & 1) * 512);
        float* skn       = reinterpret_cast<float*>(sm + OFF_SQK + ((kt & 1) ^ 1) * 512);
        const bool haveNext = (kt + 1) < NTILES;
        const int nkbase = (kt + 1) * TK;

        #pragma unroll
        for (int np = 0; np < 8; ++np) {
            float s0[4] = {0.f, 0.f, 0.f, 0.f};
            float s1[4] = {0.f, 0.f, 0.f, 0.f};
            uint32_t bT[4][4];                   // transposed K = X^T fragments
            #pragma unroll
            for (int kc = 0; kc < 4; ++kc) {
                uint32_t bH[4];
                LDSM_X4(bH, kAddrH + bufOff + (uint32_t)np * 2304 + kc * 32);
                MMA(s0, aH[kc], bH[0], bH[1]);
                MMA(s1, aH[kc], bH[2], bH[3]);
                MOVM_T(bT[kc][0], bH[0]);   // cols 0:8  x keys 0:8
                MOVM_T(bT[kc][1], bH[2]);   // cols 0:8  x keys 8:16
                MOVM_T(bT[kc][2], bH[1]);   // cols 8:16 x keys 0:8
                MOVM_T(bT[kc][3], bH[3]);   // cols 8:16 x keys 8:16
            }
            float2 nkA = *reinterpret_cast<const float2*>(&skb[np * 16 + t2]);
            float2 nkB = *reinterpret_cast<const float2*>(&skb[np * 16 + 8 + t2]);

            uint32_t wh[4];
            wh[0] = w_f16x2(fmaf(p2, s0[0], nq0 + nkA.x), fmaf(p2, s0[1], nq0 + nkA.y));
            wh[1] = w_f16x2(fmaf(p2, s0[2], nq1 + nkA.x), fmaf(p2, s0[3], nq1 + nkA.y));
            wh[2] = w_f16x2(fmaf(p2, s1[0], nq0 + nkB.x), fmaf(p2, s1[1], nq0 + nkB.y));
            wh[3] = w_f16x2(fmaf(p2, s1[2], nq1 + nkB.x), fmaf(p2, s1[3], nq1 + nkB.y));

            #pragma unroll
            for (int cp = 0; cp < 4; ++cp) {
                MMA(oacc[2 * cp],     wh, bT[cp][0], bT[cp][1]);
                MMA(oacc[2 * cp + 1], wh, bT[cp][2], bT[cp][3]);
            }
        }

        // ---- tail: stream-convert next K tile + pre-scaled norms ----
        if (haveNext) {
            #pragma unroll
            for (int i = 0; i < 8; ++i) {
                int r = gr16 + 16 * i;
                float4 v = *reinterpret_cast<const float4*>(&xb[(nkbase + r) * CDIM + c4 * 4]);
                uint32_t off = (uint32_t)r * RSTRB + (uint32_t)c4 * 8;
                *reinterpret_cast<uint2*>(sm + OFF_K + nbufOff + off) =
                    make_uint2(pack_hi(v.x, v.y), pack_hi(v.z, v.w));
                float pi = fmaf(v.x, v.x, fmaf(v.y, v.y, fmaf(v.z, v.z, v.w * v.w)));
                #pragma unroll
                for (int m = 1; m < 16; m <<= 1)
                    pi += __shfl_xor_sync(0xFFFFFFFFu, pi, m);
                if (c4 == 0) skn[r] = negs2 * pi;
            }
        }
        __syncthreads();
    }

    // ---- final: out = x + O ----
    const int r0 = qbase + wbase + g;
    const int r1 = r0 + 8;
    #pragma unroll
    for (int nt = 0; nt < 8; ++nt) {
        int c = nt * 8 + t2;
        float2 x0 = *reinterpret_cast<const float2*>(&xb[r0 * CDIM + c]);
        float2 x1 = *reinterpret_cast<const float2*>(&xb[r1 * CDIM + c]);
        float2 o0 = make_float2(x0.x + oacc[nt][0], x0.y + oacc[nt][1]);
        float2 o1 = make_float2(x1.x + oacc[nt][2], x1.y + oacc[nt][3]);
        *reinterpret_cast<float2*>(&ob[r0 * CDIM + c]) = o0;
        *reinterpret_cast<float2*>(&ob[r1 * CDIM + c]) = o1;
    }
}

extern "C" void kernel_launch(void* const* d_in, const int* in_sizes, int n_in,
                              void* d_out, int out_size) {
    const float* x       = (const float*)d_in[0];
    const float* r_sigma = (const float*)d_in[1];
    float* out           = (float*)d_out;

    cudaFuncSetAttribute(k_attention_mma9,
                         cudaFuncAttributeMaxDynamicSharedMemorySize, SMEM_DYN);

    dim3 grid(TDIM / TQ, BATCH);
    k_attention_mma9<<<grid, THREADS, SMEM_DYN>>>(x, r_sigma, out);
}